// round 13
// baseline (speedup 1.0000x reference)
#include <cuda_runtime.h>
#include <cuda_bf16.h>
#include <math.h>
#include <stdint.h>

#define B_SZ 2
#define L_SZ 2048
#define DIM 512
#define D_INNER 1024
#define D_STATE 16
#define DT_RANK 32
#define M_ROWS (B_SZ * L_SZ)   // 4096
#define NCH 32                  // scan chunks
#define CHL (L_SZ / NCH)        // 64 timesteps per chunk
#define XSPLIT 8                // x_proj K-split factor (chunk 128)

// -------- scratch (device globals; no allocation allowed) --------
__device__ __nv_bfloat16 g_hbf[M_ROWS * DIM];
__device__ __nv_bfloat16 g_wib[2 * D_INNER * DIM];
__device__ __nv_bfloat16 g_wob[DIM * D_INNER];
__device__ __nv_bfloat16 g_wxb[64 * D_INNER];
__device__ __nv_bfloat16 g_wdt[D_INNER * DT_RANK + 16];
__device__ __nv_bfloat16 g_ubf[M_ROWS * D_INNER + 16];   // pre-conv u (+pad)
__device__ __nv_bfloat16 g_zbf[M_ROWS * D_INNER];
__device__ float g_xpart[XSPLIT * M_ROWS * 64];
__device__ __nv_bfloat16 g_xdbf[M_ROWS * 64 + 16];
__device__ __nv_bfloat16 g_dlbf[M_ROWS * D_INNER];
__device__ __nv_bfloat16 g_ygbf[M_ROWS * D_INNER];
__device__ float g_hend[B_SZ * NCH * D_INNER * D_STATE];
__device__ float g_sumdl[B_SZ * NCH * D_INNER];
__device__ float g_hin[B_SZ * NCH * D_INNER * D_STATE];

// ============================ PTX helpers ============================
__device__ __forceinline__ uint32_t smem_u32(const void* p) {
    uint32_t a;
    asm("{ .reg .u64 t; cvta.to.shared.u64 t, %1; cvt.u32.u64 %0, t; }"
        : "=r"(a) : "l"(p));
    return a;
}
__device__ __forceinline__ void ldsm_x4(uint32_t& r0, uint32_t& r1,
                                        uint32_t& r2, uint32_t& r3, uint32_t a) {
    asm volatile("ldmatrix.sync.aligned.m8n8.x4.shared.b16 {%0,%1,%2,%3}, [%4];"
                 : "=r"(r0), "=r"(r1), "=r"(r2), "=r"(r3) : "r"(a));
}
__device__ __forceinline__ void mma16816(float* c, uint32_t a0, uint32_t a1,
                                         uint32_t a2, uint32_t a3,
                                         uint32_t b0, uint32_t b1) {
    asm volatile(
        "mma.sync.aligned.m16n8k16.row.col.f32.bf16.bf16.f32 "
        "{%0,%1,%2,%3}, {%4,%5,%6,%7}, {%8,%9}, {%0,%1,%2,%3};"
        : "+f"(c[0]), "+f"(c[1]), "+f"(c[2]), "+f"(c[3])
        : "r"(a0), "r"(a1), "r"(a2), "r"(a3), "r"(b0), "r"(b1));
}
__device__ __forceinline__ void cp16(uint32_t dst, const void* src) {
    asm volatile("cp.async.cg.shared.global [%0], [%1], 16;" :: "r"(dst), "l"(src));
}
__device__ __forceinline__ void cp_commit() {
    asm volatile("cp.async.commit_group;" ::: "memory");
}
__device__ __forceinline__ void cp_wait1() {
    asm volatile("cp.async.wait_group 1;" ::: "memory");
}
__device__ __forceinline__ void sts16(uint32_t dst, uint4 v) {
    asm volatile("st.shared.v4.b32 [%0], {%1,%2,%3,%4};"
                 :: "r"(dst), "r"(v.x), "r"(v.y), "r"(v.z), "r"(v.w) : "memory");
}
__device__ __forceinline__ float softplus_f(float x) {
    return x > 20.f ? x : log1pf(expf(x));
}
__device__ __forceinline__ void ld16bf(const __nv_bfloat16* p, float* o) {
    union { uint4 u; __nv_bfloat162 h[4]; } A, B;
    A.u = *reinterpret_cast<const uint4*>(p);
    B.u = *reinterpret_cast<const uint4*>(p + 8);
#pragma unroll
    for (int i = 0; i < 4; i++) {
        float2 f = __bfloat1622float2(A.h[i]);
        o[i * 2] = f.x; o[i * 2 + 1] = f.y;
        f = __bfloat1622float2(B.h[i]);
        o[8 + i * 2] = f.x; o[8 + i * 2 + 1] = f.y;
    }
}

// ============================ HMMA bf16 GEMM (3-stage pipeline) ============================
// EPI: 0 fp32 (SPLITK partials), 1 fp32+residual, 2 split u/z bf16,
//      4 softplus(acc+bias)->bf16, 5 bf16
// CONVA: A operand computed on the fly = silu(causal depthwise conv4(A_raw))
template <int BN, int EPI, int SPLITK, int CONVA>
__global__ void __launch_bounds__(256)
hmma_gemm(const __nv_bfloat16* __restrict__ A, int lda,
          const __nv_bfloat16* __restrict__ W, int ldw,
          float* __restrict__ C, int ldc, int K,
          const float* __restrict__ res,
          __nv_bfloat16* __restrict__ uout,
          __nv_bfloat16* __restrict__ zout,
          const float* __restrict__ cw,
          const float* __restrict__ cb) {
    constexpr int AM = (BN == 128) ? 4 : 2;
    constexpr int STG = (128 + BN) * 80;
    constexpr int CH_TOT = (128 + BN) * 5;
    extern __shared__ __align__(16) char sm[];

    const int tid = threadIdx.x;
    const int lane = tid & 31;
    const int wid = tid >> 5;
    const int m0 = blockIdx.y * 128;
    const int n0 = blockIdx.x * BN;
    const int wm = (BN == 128) ? (wid & 1) * 64 : (wid & 3) * 32;
    const int wn = (BN == 128) ? (wid >> 1) * 32 : (wid >> 2) * 32;

    const int kz_g = SPLITK ? blockIdx.z * SPLITK : 0;
    if (SPLITK) {
        A += kz_g; W += kz_g;
        C += (size_t)blockIdx.z * M_ROWS * 64;   // private partial buffer
    }
    const int KT = (SPLITK ? SPLITK : K) >> 5;

    const uint32_t smb = smem_u32(sm);

    uint32_t aoff[AM], boff[2];
#pragma unroll
    for (int mi = 0; mi < AM; mi++)
        aoff[mi] = (uint32_t)(wm + mi * 16 + (lane & 15)) * 80 + ((lane >> 4) & 1) * 16;
#pragma unroll
    for (int ni = 0; ni < 2; ni++)
        boff[ni] = 128 * 80
                 + (uint32_t)(wn + ni * 16 + (lane & 7) + ((lane >> 4) & 1) * 8) * 80
                 + ((lane >> 3) & 1) * 16;

    float acc[AM][4][4];
#pragma unroll
    for (int i = 0; i < AM; i++)
#pragma unroll
        for (int j = 0; j < 4; j++)
#pragma unroll
            for (int q = 0; q < 4; q++) acc[i][j][q] = 0.f;

    auto load_stage = [&](int kt, int st) {
        const int k0 = kt * 32;
        const uint32_t base = smb + st * STG;
        for (int c = tid; c < CH_TOT; c += 256) {
            const int row = c / 5, col = c % 5;
            const uint32_t dst = base + row * 80 + col * 16;
            if (row < 128) {
                if (CONVA) {
                    if (col == 4) continue;   // bytes 64..79 never consumed
                    const int gm = m0 + row;
                    const int l = gm & (L_SZ - 1);
                    const int ch0 = kz_g + k0 + col * 8;
                    const __nv_bfloat16* bu = A + (size_t)gm * lda + k0 + col * 8;
                    float uu[4][8];
#pragma unroll
                    for (int j = 0; j < 4; j++) {
                        if (l >= 3 - j) {
                            uint4 raw = *reinterpret_cast<const uint4*>(bu + (j - 3) * lda);
                            const __nv_bfloat162* hh =
                                reinterpret_cast<const __nv_bfloat162*>(&raw);
#pragma unroll
                            for (int i = 0; i < 4; i++) {
                                const float2 f = __bfloat1622float2(hh[i]);
                                uu[j][2 * i] = f.x; uu[j][2 * i + 1] = f.y;
                            }
                        } else {
#pragma unroll
                            for (int i = 0; i < 8; i++) uu[j][i] = 0.f;
                        }
                    }
                    float s[8];
#pragma unroll
                    for (int i = 0; i < 8; i++) {
                        const float4 w4 = __ldg(
                            reinterpret_cast<const float4*>(cw + (ch0 + i) * 4));
                        float a = __ldg(cb + ch0 + i);
                        a = fmaf(w4.x, uu[0][i], a);
                        a = fmaf(w4.y, uu[1][i], a);
                        a = fmaf(w4.z, uu[2][i], a);
                        a = fmaf(w4.w, uu[3][i], a);
                        s[i] = a / (1.0f + __expf(-a));
                    }
                    uint4 pk;
                    __nv_bfloat162 h0 = __float22bfloat162_rn(make_float2(s[0], s[1]));
                    __nv_bfloat162 h1 = __float22bfloat162_rn(make_float2(s[2], s[3]));
                    __nv_bfloat162 h2 = __float22bfloat162_rn(make_float2(s[4], s[5]));
                    __nv_bfloat162 h3 = __float22bfloat162_rn(make_float2(s[6], s[7]));
                    pk.x = *reinterpret_cast<uint32_t*>(&h0);
                    pk.y = *reinterpret_cast<uint32_t*>(&h1);
                    pk.z = *reinterpret_cast<uint32_t*>(&h2);
                    pk.w = *reinterpret_cast<uint32_t*>(&h3);
                    sts16(dst, pk);
                } else {
                    cp16(dst, A + (size_t)(m0 + row) * lda + k0 + col * 8);
                }
            } else {
                cp16(dst, W + (size_t)(n0 + row - 128) * ldw + k0 + col * 8);
            }
        }
    };

    load_stage(0, 0); cp_commit();
    if (KT > 1) { load_stage(1, 1); cp_commit(); }
    else cp_commit();

    for (int kt = 0; kt < KT; kt++) {
        cp_wait1();
        __syncthreads();
        if (kt + 2 < KT) load_stage(kt + 2, (kt + 2) % 3);
        cp_commit();

        const uint32_t sbase = smb + (kt % 3) * STG;
#pragma unroll
        for (int kk = 0; kk < 2; kk++) {
            const uint32_t ko = kk * 32;
            uint32_t a[AM][4], b2[4][2];
#pragma unroll
            for (int mi = 0; mi < AM; mi++)
                ldsm_x4(a[mi][0], a[mi][1], a[mi][2], a[mi][3], sbase + aoff[mi] + ko);
#pragma unroll
            for (int ni = 0; ni < 2; ni++) {
                uint32_t r0, r1, r2, r3;
                ldsm_x4(r0, r1, r2, r3, sbase + boff[ni] + ko);
                b2[ni * 2 + 0][0] = r0; b2[ni * 2 + 0][1] = r1;
                b2[ni * 2 + 1][0] = r2; b2[ni * 2 + 1][1] = r3;
            }
#pragma unroll
            for (int mi = 0; mi < AM; mi++)
#pragma unroll
                for (int nj = 0; nj < 4; nj++)
                    mma16816(acc[mi][nj], a[mi][0], a[mi][1], a[mi][2], a[mi][3],
                             b2[nj][0], b2[nj][1]);
        }
        if (CONVA) __syncthreads();   // protect next stage's STS vs this stage's reads
    }

#pragma unroll
    for (int mi = 0; mi < AM; mi++) {
        const int r0 = m0 + wm + mi * 16 + (lane >> 2);
#pragma unroll
        for (int nj = 0; nj < 4; nj++) {
            const int c = n0 + wn + nj * 8 + (lane & 3) * 2;
            float2 v0 = make_float2(acc[mi][nj][0], acc[mi][nj][1]);
            float2 v1 = make_float2(acc[mi][nj][2], acc[mi][nj][3]);
            if (EPI == 2) {
                __nv_bfloat162 p0 = __float22bfloat162_rn(v0);
                __nv_bfloat162 p1 = __float22bfloat162_rn(v1);
                __nv_bfloat16* dst = (c >= 1024) ? zout : uout;
                const int cc = (c >= 1024) ? c - 1024 : c;
                *reinterpret_cast<__nv_bfloat162*>(dst + (size_t)r0 * 1024 + cc) = p0;
                *reinterpret_cast<__nv_bfloat162*>(dst + (size_t)(r0 + 8) * 1024 + cc) = p1;
            } else if (EPI == 4 || EPI == 5) {
                if (EPI == 4) {
                    const float2 bb = *reinterpret_cast<const float2*>(res + c);
                    v0.x = softplus_f(v0.x + bb.x); v0.y = softplus_f(v0.y + bb.y);
                    v1.x = softplus_f(v1.x + bb.x); v1.y = softplus_f(v1.y + bb.y);
                }
                __nv_bfloat162 p0 = __float22bfloat162_rn(v0);
                __nv_bfloat162 p1 = __float22bfloat162_rn(v1);
                *reinterpret_cast<__nv_bfloat162*>(uout + (size_t)r0 * ldc + c) = p0;
                *reinterpret_cast<__nv_bfloat162*>(uout + (size_t)(r0 + 8) * ldc + c) = p1;
            } else {
                const size_t o0 = (size_t)r0 * ldc + c;
                const size_t o1 = (size_t)(r0 + 8) * ldc + c;
                if (EPI == 1) {
                    const float2 q0 = *reinterpret_cast<const float2*>(res + o0);
                    const float2 q1 = *reinterpret_cast<const float2*>(res + o1);
                    v0.x += q0.x; v0.y += q0.y; v1.x += q1.x; v1.y += q1.y;
                }
                *reinterpret_cast<float2*>(C + o0) = v0;
                *reinterpret_cast<float2*>(C + o1) = v1;
            }
        }
    }
}

// ============================ x_proj partial combine ============================
__global__ void xcombine(const float* __restrict__ p, __nv_bfloat16* __restrict__ out) {
    const int i = blockIdx.x * blockDim.x + threadIdx.x;
    const float4* q = reinterpret_cast<const float4*>(p);
    const int Q = M_ROWS * 64 / 4;
    float4 a = q[i];
#pragma unroll
    for (int s = 1; s < XSPLIT; s++) {
        const float4 b = q[i + s * Q];
        a.x += b.x; a.y += b.y; a.z += b.z; a.w += b.w;
    }
    __nv_bfloat162 p0 = __float22bfloat162_rn(make_float2(a.x, a.y));
    __nv_bfloat162 p1 = __float22bfloat162_rn(make_float2(a.z, a.w));
    uint2 pk;
    pk.x = *reinterpret_cast<uint32_t*>(&p0);
    pk.y = *reinterpret_cast<uint32_t*>(&p1);
    *reinterpret_cast<uint2*>(out + i * 4) = pk;
}

// ============================ fused weight-convert + LayerNorm ============================
__global__ void prep_kernel(const float* __restrict__ w1, __nv_bfloat16* __restrict__ o1,
                            const float* __restrict__ w2, __nv_bfloat16* __restrict__ o2,
                            const float* __restrict__ w3, __nv_bfloat16* __restrict__ o3,
                            const float* __restrict__ w4, __nv_bfloat16* __restrict__ o4,
                            const float* __restrict__ x,
                            const float* __restrict__ gamma,
                            const float* __restrict__ beta,
                            __nv_bfloat16* __restrict__ hout) {
    int blk = blockIdx.x;
    if (blk >= 1632) {
        const int row = (blk - 1632) * 8 + (threadIdx.x >> 5);
        const int lane = threadIdx.x & 31;
        const float4* xr = reinterpret_cast<const float4*>(x + (size_t)row * DIM);
        float4 v[4];
        float s = 0.f, q = 0.f;
#pragma unroll
        for (int j = 0; j < 4; j++) {
            v[j] = xr[lane + 32 * j];
            s += v[j].x + v[j].y + v[j].z + v[j].w;
            q += v[j].x * v[j].x + v[j].y * v[j].y + v[j].z * v[j].z + v[j].w * v[j].w;
        }
#pragma unroll
        for (int o = 16; o; o >>= 1) {
            s += __shfl_xor_sync(~0u, s, o);
            q += __shfl_xor_sync(~0u, q, o);
        }
        const float mean = s * (1.0f / DIM);
        const float var  = q * (1.0f / DIM) - mean * mean;
        const float inv  = rsqrtf(var + 1e-5f);
        uint2* orow = reinterpret_cast<uint2*>(hout + (size_t)row * DIM);
#pragma unroll
        for (int j = 0; j < 4; j++) {
            const float4 gv = reinterpret_cast<const float4*>(gamma)[lane + 32 * j];
            const float4 bv = reinterpret_cast<const float4*>(beta)[lane + 32 * j];
            float4 o4;
            o4.x = (v[j].x - mean) * inv * gv.x + bv.x;
            o4.y = (v[j].y - mean) * inv * gv.y + bv.y;
            o4.z = (v[j].z - mean) * inv * gv.z + bv.z;
            o4.w = (v[j].w - mean) * inv * gv.w + bv.w;
            __nv_bfloat162 p0 = __float22bfloat162_rn(make_float2(o4.x, o4.y));
            __nv_bfloat162 p1 = __float22bfloat162_rn(make_float2(o4.z, o4.w));
            uint2 pk;
            pk.x = *reinterpret_cast<uint32_t*>(&p0);
            pk.y = *reinterpret_cast<uint32_t*>(&p1);
            orow[lane + 32 * j] = pk;
        }
        return;
    }
    const float* in; __nv_bfloat16* out;
    if (blk < 1024) { in = w1; out = o1; }
    else if (blk < 1536) { in = w2; out = o2; blk -= 1024; }
    else if (blk < 1600) { in = w3; out = o3; blk -= 1536; }
    else { in = w4; out = o4; blk -= 1600; }
    const int i = blk * 256 + threadIdx.x;
    const float4 v = reinterpret_cast<const float4*>(in)[i];
    __nv_bfloat162 p0 = __float22bfloat162_rn(make_float2(v.x, v.y));
    __nv_bfloat162 p1 = __float22bfloat162_rn(make_float2(v.z, v.w));
    reinterpret_cast<__nv_bfloat162*>(out)[i * 2 + 0] = p0;
    reinterpret_cast<__nv_bfloat162*>(out)[i * 2 + 1] = p1;
}

// ============================ chunked parallel scan ============================
__device__ __forceinline__ void pow_ladder(float q, float* dA) {
    const float q2 = q * q;
    const float q4 = q2 * q2;
    const float q8 = q4 * q4;
    dA[0] = q;       dA[1] = q2;      dA[2] = q2 * q;  dA[3] = q4;
    dA[4] = q4 * q;  dA[5] = q4 * q2; dA[6] = dA[5] * q; dA[7] = q8;
#pragma unroll
    for (int i = 0; i < 8; i++) dA[8 + i] = q8 * dA[i];
}

__device__ __forceinline__ bool seq_check(const float* A_log, int d, float* Ac) {
    bool seq = true;
#pragma unroll
    for (int i = 0; i < 4; i++) {
        const float4 v = reinterpret_cast<const float4*>(A_log + d * 16)[i];
        Ac[i * 4 + 0] = -__expf(v.x); Ac[i * 4 + 1] = -__expf(v.y);
        Ac[i * 4 + 2] = -__expf(v.z); Ac[i * 4 + 3] = -__expf(v.w);
    }
#pragma unroll
    for (int n = 0; n < 16; n++)
        seq = seq && (fabsf(Ac[n] + (float)(n + 1)) < 1e-3f * (float)(n + 1));
    return seq;
}

__global__ void scan_p1(const __nv_bfloat16* __restrict__ delta,
                        const __nv_bfloat16* __restrict__ ubf,
                        const __nv_bfloat16* __restrict__ xdbf,
                        const float* __restrict__ A_log,
                        const float* __restrict__ cw,
                        const float* __restrict__ cb,
                        float* __restrict__ hend,
                        float* __restrict__ sumdl) {
    const int t = blockIdx.x * blockDim.x + threadIdx.x;
    const int d = t & 1023;
    const int ch = (t >> 10) & (NCH - 1);
    const int b = t >> 15;

    float Ac[16];
    const bool seq = seq_check(A_log, d, Ac);

    const size_t rb = (size_t)(b * L_SZ + ch * CHL);
    const __nv_bfloat16* dr = delta + rb * D_INNER + d;
    const __nv_bfloat16* ur = ubf + rb * D_INNER + d;
    const __nv_bfloat16* xd = xdbf + rb * 64;

    // conv state
    const float4 w4 = __ldg(reinterpret_cast<const float4*>(cw + d * 4));
    const float cbias = __ldg(cb + d);
    float v1, v2, v3;
    if (ch == 0) { v1 = v2 = v3 = 0.f; }
    else {
        v1 = __bfloat162float(__ldg(ur - 3 * D_INNER));
        v2 = __bfloat162float(__ldg(ur - 2 * D_INNER));
        v3 = __bfloat162float(__ldg(ur - 1 * D_INNER));
    }

    float h[16];
#pragma unroll
    for (int n = 0; n < 16; n++) h[n] = 0.f;
    float sdl = 0.f;

#pragma unroll 2
    for (int l = 0; l < CHL; l++) {
        const float dl = __bfloat162float(__ldg(dr + l * D_INNER));
        const float un = __bfloat162float(__ldg(ur + l * D_INNER));
        float ca = cbias;
        ca = fmaf(w4.x, v1, ca); ca = fmaf(w4.y, v2, ca);
        ca = fmaf(w4.z, v3, ca); ca = fmaf(w4.w, un, ca);
        v1 = v2; v2 = v3; v3 = un;
        const float uv = ca / (1.0f + __expf(-ca));
        float Bv[16];
        ld16bf(xd + l * 64 + DT_RANK, Bv);
        sdl += dl;
        const float du = dl * uv;
        if (seq) {
            float dA[16];
            pow_ladder(__expf(-dl), dA);
#pragma unroll
            for (int n = 0; n < 16; n++)
                h[n] = fmaf(dA[n], h[n], du * Bv[n]);
        } else {
#pragma unroll
            for (int n = 0; n < 16; n++)
                h[n] = fmaf(__expf(dl * Ac[n]), h[n], du * Bv[n]);
        }
    }

    float4* he = reinterpret_cast<float4*>(hend + ((size_t)((b * NCH + ch) * 1024 + d)) * 16);
#pragma unroll
    for (int i = 0; i < 4; i++)
        he[i] = make_float4(h[i*4], h[i*4+1], h[i*4+2], h[i*4+3]);
    sumdl[(b * NCH + ch) * 1024 + d] = sdl;
}

__global__ void scan_p2(const float* __restrict__ hend,
                        const float* __restrict__ sumdl,
                        const float* __restrict__ A_log,
                        float* __restrict__ hin) {
    const int t = blockIdx.x * blockDim.x + threadIdx.x;
    const int n = t & 15;
    const int d = (t >> 4) & 1023;
    const int b = t >> 14;

    const float Ac = -__expf(A_log[d * 16 + n]);
    float h = 0.f;
#pragma unroll
    for (int ch = 0; ch < NCH; ch++) {
        const size_t ix = ((size_t)((b * NCH + ch) * 1024 + d)) * 16 + n;
        hin[ix] = h;
        const float P = __expf(Ac * sumdl[(b * NCH + ch) * 1024 + d]);
        h = fmaf(P, h, hend[ix]);
    }
}

__global__ void scan_p3(const __nv_bfloat16* __restrict__ delta,
                        const __nv_bfloat16* __restrict__ ubf,
                        const __nv_bfloat16* __restrict__ xdbf,
                        const __nv_bfloat16* __restrict__ zbf,
                        const float* __restrict__ A_log,
                        const float* __restrict__ cw,
                        const float* __restrict__ cb,
                        const float* __restrict__ Dp,
                        const float* __restrict__ hin,
                        __nv_bfloat16* __restrict__ yg) {
    const int t = blockIdx.x * blockDim.x + threadIdx.x;
    const int d = t & 1023;
    const int ch = (t >> 10) & (NCH - 1);
    const int b = t >> 15;

    float Ac[16];
    const bool seq = seq_check(A_log, d, Ac);
    const float Dd = Dp[d];

    float h[16];
    const float4* hi = reinterpret_cast<const float4*>(
        hin + ((size_t)((b * NCH + ch) * 1024 + d)) * 16);
#pragma unroll
    for (int i = 0; i < 4; i++) {
        const float4 v = hi[i];
        h[i*4+0]=v.x; h[i*4+1]=v.y; h[i*4+2]=v.z; h[i*4+3]=v.w;
    }

    const size_t rb = (size_t)(b * L_SZ + ch * CHL);
    const __nv_bfloat16* dr = delta + rb * D_INNER + d;
    const __nv_bfloat16* ur = ubf + rb * D_INNER + d;
    const __nv_bfloat16* xd = xdbf + rb * 64;
    const __nv_bfloat16* zr = zbf + rb * D_INNER + d;
    __nv_bfloat16* yo = yg + rb * D_INNER + d;

    const float4 w4 = __ldg(reinterpret_cast<const float4*>(cw + d * 4));
    const float cbias = __ldg(cb + d);
    float v1, v2, v3;
    if (ch == 0) { v1 = v2 = v3 = 0.f; }
    else {
        v1 = __bfloat162float(__ldg(ur - 3 * D_INNER));
        v2 = __bfloat162float(__ldg(ur - 2 * D_INNER));
        v3 = __bfloat162float(__ldg(ur - 1 * D_INNER));
    }

#pragma unroll 2
    for (int l = 0; l < CHL; l++) {
        const float dl = __bfloat162float(__ldg(dr + l * D_INNER));
        const float un = __bfloat162float(__ldg(ur + l * D_INNER));
        float ca = cbias;
        ca = fmaf(w4.x, v1, ca); ca = fmaf(w4.y, v2, ca);
        ca = fmaf(w4.z, v3, ca); ca = fmaf(w4.w, un, ca);
        v1 = v2; v2 = v3; v3 = un;
        const float uv = ca / (1.0f + __expf(-ca));
        float Bv[16], Cv[16];
        ld16bf(xd + l * 64 + DT_RANK, Bv);
        ld16bf(xd + l * 64 + DT_RANK + D_STATE, Cv);
        const float du = dl * uv;
        float yv = 0.f;
        if (seq) {
            float dA[16];
            pow_ladder(__expf(-dl), dA);
#pragma unroll
            for (int n = 0; n < 16; n++) {
                h[n] = fmaf(dA[n], h[n], du * Bv[n]);
                yv = fmaf(h[n], Cv[n], yv);
            }
        } else {
#pragma unroll
            for (int n = 0; n < 16; n++) {
                h[n] = fmaf(__expf(dl * Ac[n]), h[n], du * Bv[n]);
                yv = fmaf(h[n], Cv[n], yv);
            }
        }
        const float z = __bfloat162float(zr[l * D_INNER]);
        const float sg = z / (1.0f + __expf(-z));
        yo[l * D_INNER] = __float2bfloat16((yv + uv * Dd) * sg);
    }
}

// ============================ launch ============================
extern "C" void kernel_launch(void* const* d_in, const int* in_sizes, int n_in,
                              void* d_out, int out_size) {
    const float* x         = (const float*)d_in[0];
    const float* gamma     = (const float*)d_in[2];
    const float* beta      = (const float*)d_in[3];
    const float* in_proj_w = (const float*)d_in[4];
    const float* conv_w    = (const float*)d_in[5];
    const float* conv_b    = (const float*)d_in[6];
    const float* x_proj_w  = (const float*)d_in[7];
    const float* dt_proj_w = (const float*)d_in[8];
    const float* dt_proj_b = (const float*)d_in[9];
    const float* A_log     = (const float*)d_in[10];
    const float* Dp        = (const float*)d_in[11];
    const float* out_proj_w= (const float*)d_in[12];
    float* out = (float*)d_out;

    __nv_bfloat16 *hbf_, *wib_, *wob_, *wxb_, *wdt_, *ubf_, *zbf_, *xdbf_, *dlbf_, *ygbf_;
    float *xp_, *he_, *sd_, *hi_;
    cudaGetSymbolAddress((void**)&hbf_, g_hbf);
    cudaGetSymbolAddress((void**)&wib_, g_wib);
    cudaGetSymbolAddress((void**)&wob_, g_wob);
    cudaGetSymbolAddress((void**)&wxb_, g_wxb);
    cudaGetSymbolAddress((void**)&wdt_, g_wdt);
    cudaGetSymbolAddress((void**)&ubf_, g_ubf);
    cudaGetSymbolAddress((void**)&zbf_, g_zbf);
    cudaGetSymbolAddress((void**)&xp_, g_xpart);
    cudaGetSymbolAddress((void**)&xdbf_, g_xdbf);
    cudaGetSymbolAddress((void**)&dlbf_, g_dlbf);
    cudaGetSymbolAddress((void**)&ygbf_, g_ygbf);
    cudaGetSymbolAddress((void**)&he_, g_hend);
    cudaGetSymbolAddress((void**)&sd_, g_sumdl);
    cudaGetSymbolAddress((void**)&hi_, g_hin);

    cudaFuncSetAttribute(hmma_gemm<128, 2, 0, 0>,
                         cudaFuncAttributeMaxDynamicSharedMemorySize, 61440);

    // 0+1. weight conversions + LayerNorm (single launch)
    prep_kernel<<<2144, 256>>>(in_proj_w, wib_, out_proj_w, wob_,
                               x_proj_w, wxb_, dt_proj_w, wdt_,
                               x, gamma, beta, hbf_);

    // 2. in_proj: u | z both bf16, K=512, BN=128
    hmma_gemm<128, 2, 0, 0><<<dim3(16, 32), 256, 61440>>>(
        hbf_, DIM, wib_, DIM, nullptr, 1024, DIM, nullptr, ubf_, zbf_,
        nullptr, nullptr);

    // 3+4. x_proj with fused conv+silu A-operand; K split 8x128 -> partials -> bf16
    hmma_gemm<64, 0, 128, 1><<<dim3(1, 32, XSPLIT), 256, 46080>>>(
        ubf_, D_INNER, wxb_, D_INNER, xp_, 64, D_INNER, nullptr, nullptr, nullptr,
        conv_w, conv_b);
    xcombine<<<M_ROWS * 64 / 4 / 256, 256>>>(xp_, xdbf_);

    // 5. dt_proj + softplus -> bf16 delta, K=32
    hmma_gemm<64, 4, 0, 0><<<dim3(16, 32), 256, 46080>>>(
        xdbf_, 64, wdt_, DT_RANK, nullptr, 1024, DT_RANK, dt_proj_b, dlbf_, nullptr,
        nullptr, nullptr);

    // 6. chunked scan (3 passes, NCH=32, conv fused via rolling window)
    scan_p1<<<B_SZ * NCH * D_INNER / 256, 256>>>(dlbf_, ubf_, xdbf_, A_log,
                                                 conv_w, conv_b, he_, sd_);
    scan_p2<<<B_SZ * D_INNER * D_STATE / 256, 256>>>(he_, sd_, A_log, hi_);
    scan_p3<<<B_SZ * NCH * D_INNER / 256, 256>>>(dlbf_, ubf_, xdbf_, zbf_, A_log,
                                                 conv_w, conv_b, Dp, hi_, ygbf_);

    // 7. out_proj + residual
    hmma_gemm<64, 1, 0, 0><<<dim3(DIM / 64, 32), 256, 46080>>>(
        ygbf_, D_INNER, wob_, D_INNER, out, DIM, D_INNER, x, nullptr, nullptr,
        nullptr, nullptr);
}

// round 14
// speedup vs baseline: 1.2642x; 1.2642x over previous
#include <cuda_runtime.h>
#include <cuda_bf16.h>
#include <math.h>
#include <stdint.h>

#define B_SZ 2
#define L_SZ 2048
#define DIM 512
#define D_INNER 1024
#define D_STATE 16
#define DT_RANK 32
#define M_ROWS (B_SZ * L_SZ)   // 4096
#define NCH 32                  // scan chunks
#define CHL (L_SZ / NCH)        // 64 timesteps per chunk
#define XSPLIT 8                // x_proj K-split factor

// -------- scratch (device globals; no allocation allowed) --------
__device__ __nv_bfloat16 g_hbf[M_ROWS * DIM];
__device__ __nv_bfloat16 g_wib[2 * D_INNER * DIM];
__device__ __nv_bfloat16 g_wob[DIM * D_INNER];
__device__ __nv_bfloat16 g_wxb[64 * D_INNER];
__device__ __nv_bfloat16 g_wdt[D_INNER * DT_RANK + 16];
__device__ __nv_bfloat16 g_ubf[M_ROWS * D_INNER];
__device__ __nv_bfloat16 g_zbf[M_ROWS * D_INNER];
__device__ __nv_bfloat16 g_uabf[M_ROWS * D_INNER];
__device__ float g_xpart[XSPLIT * M_ROWS * 64];
__device__ __nv_bfloat16 g_xdbf[M_ROWS * 64 + 16];
__device__ __nv_bfloat16 g_dlbf[M_ROWS * D_INNER];
__device__ __nv_bfloat16 g_ygbf[M_ROWS * D_INNER];
__device__ float g_hend[B_SZ * NCH * D_INNER * D_STATE];
__device__ float g_sumdl[B_SZ * NCH * D_INNER];
__device__ float g_hin[B_SZ * NCH * D_INNER * D_STATE];

// ============================ PTX helpers ============================
__device__ __forceinline__ uint32_t smem_u32(const void* p) {
    uint32_t a;
    asm("{ .reg .u64 t; cvta.to.shared.u64 t, %1; cvt.u32.u64 %0, t; }"
        : "=r"(a) : "l"(p));
    return a;
}
__device__ __forceinline__ void ldsm_x4(uint32_t& r0, uint32_t& r1,
                                        uint32_t& r2, uint32_t& r3, uint32_t a) {
    asm volatile("ldmatrix.sync.aligned.m8n8.x4.shared.b16 {%0,%1,%2,%3}, [%4];"
                 : "=r"(r0), "=r"(r1), "=r"(r2), "=r"(r3) : "r"(a));
}
__device__ __forceinline__ void mma16816(float* c, uint32_t a0, uint32_t a1,
                                         uint32_t a2, uint32_t a3,
                                         uint32_t b0, uint32_t b1) {
    asm volatile(
        "mma.sync.aligned.m16n8k16.row.col.f32.bf16.bf16.f32 "
        "{%0,%1,%2,%3}, {%4,%5,%6,%7}, {%8,%9}, {%0,%1,%2,%3};"
        : "+f"(c[0]), "+f"(c[1]), "+f"(c[2]), "+f"(c[3])
        : "r"(a0), "r"(a1), "r"(a2), "r"(a3), "r"(b0), "r"(b1));
}
__device__ __forceinline__ void cp16(uint32_t dst, const void* src) {
    asm volatile("cp.async.cg.shared.global [%0], [%1], 16;" :: "r"(dst), "l"(src));
}
__device__ __forceinline__ void cp_commit() {
    asm volatile("cp.async.commit_group;" ::: "memory");
}
__device__ __forceinline__ void cp_wait1() {
    asm volatile("cp.async.wait_group 1;" ::: "memory");
}
__device__ __forceinline__ float softplus_f(float x) {
    return x > 20.f ? x : log1pf(expf(x));
}
__device__ __forceinline__ void ld16bf(const __nv_bfloat16* p, float* o) {
    union { uint4 u; __nv_bfloat162 h[4]; } A, B;
    A.u = *reinterpret_cast<const uint4*>(p);
    B.u = *reinterpret_cast<const uint4*>(p + 8);
#pragma unroll
    for (int i = 0; i < 4; i++) {
        float2 f = __bfloat1622float2(A.h[i]);
        o[i * 2] = f.x; o[i * 2 + 1] = f.y;
        f = __bfloat1622float2(B.h[i]);
        o[8 + i * 2] = f.x; o[8 + i * 2 + 1] = f.y;
    }
}

// ============================ HMMA bf16 GEMM (3-stage pipeline) ============================
// EPI: 0 fp32 (SPLITK partials), 1 fp32+residual, 2 split u/z bf16,
//      4 softplus(acc+bias)->bf16, 5 bf16
template <int BN, int EPI, int SPLITK>
__global__ void __launch_bounds__(256)
hmma_gemm(const __nv_bfloat16* __restrict__ A, int lda,
          const __nv_bfloat16* __restrict__ W, int ldw,
          float* __restrict__ C, int ldc, int K,
          const float* __restrict__ res,
          __nv_bfloat16* __restrict__ uout,
          __nv_bfloat16* __restrict__ zout) {
    constexpr int AM = (BN == 128) ? 4 : 2;
    constexpr int STG = (128 + BN) * 80;
    constexpr int CH_TOT = (128 + BN) * 5;
    extern __shared__ __align__(16) char sm[];

    const int tid = threadIdx.x;
    const int lane = tid & 31;
    const int wid = tid >> 5;
    const int m0 = blockIdx.y * 128;
    const int n0 = blockIdx.x * BN;
    const int wm = (BN == 128) ? (wid & 1) * 64 : (wid & 3) * 32;
    const int wn = (BN == 128) ? (wid >> 1) * 32 : (wid >> 2) * 32;

    if (SPLITK) {
        const int kz = blockIdx.z * SPLITK;
        A += kz; W += kz;
        C += (size_t)blockIdx.z * M_ROWS * 64;   // private partial buffer
    }
    const int KT = (SPLITK ? SPLITK : K) >> 5;

    const uint32_t smb = smem_u32(sm);

    uint32_t aoff[AM], boff[2];
#pragma unroll
    for (int mi = 0; mi < AM; mi++)
        aoff[mi] = (uint32_t)(wm + mi * 16 + (lane & 15)) * 80 + ((lane >> 4) & 1) * 16;
#pragma unroll
    for (int ni = 0; ni < 2; ni++)
        boff[ni] = 128 * 80
                 + (uint32_t)(wn + ni * 16 + (lane & 7) + ((lane >> 4) & 1) * 8) * 80
                 + ((lane >> 3) & 1) * 16;

    float acc[AM][4][4];
#pragma unroll
    for (int i = 0; i < AM; i++)
#pragma unroll
        for (int j = 0; j < 4; j++)
#pragma unroll
            for (int q = 0; q < 4; q++) acc[i][j][q] = 0.f;

    auto load_stage = [&](int kt, int st) {
        const int k0 = kt * 32;
        const uint32_t base = smb + st * STG;
        for (int c = tid; c < CH_TOT; c += 256) {
            const int row = c / 5, col = c % 5;
            const uint32_t dst = base + row * 80 + col * 16;
            if (row < 128)
                cp16(dst, A + (size_t)(m0 + row) * lda + k0 + col * 8);
            else
                cp16(dst, W + (size_t)(n0 + row - 128) * ldw + k0 + col * 8);
        }
    };

    load_stage(0, 0); cp_commit();
    if (KT > 1) { load_stage(1, 1); cp_commit(); }
    else cp_commit();

    for (int kt = 0; kt < KT; kt++) {
        cp_wait1();
        __syncthreads();
        if (kt + 2 < KT) load_stage(kt + 2, (kt + 2) % 3);
        cp_commit();

        const uint32_t sbase = smb + (kt % 3) * STG;
#pragma unroll
        for (int kk = 0; kk < 2; kk++) {
            const uint32_t ko = kk * 32;
            uint32_t a[AM][4], b2[4][2];
#pragma unroll
            for (int mi = 0; mi < AM; mi++)
                ldsm_x4(a[mi][0], a[mi][1], a[mi][2], a[mi][3], sbase + aoff[mi] + ko);
#pragma unroll
            for (int ni = 0; ni < 2; ni++) {
                uint32_t r0, r1, r2, r3;
                ldsm_x4(r0, r1, r2, r3, sbase + boff[ni] + ko);
                b2[ni * 2 + 0][0] = r0; b2[ni * 2 + 0][1] = r1;
                b2[ni * 2 + 1][0] = r2; b2[ni * 2 + 1][1] = r3;
            }
#pragma unroll
            for (int mi = 0; mi < AM; mi++)
#pragma unroll
                for (int nj = 0; nj < 4; nj++)
                    mma16816(acc[mi][nj], a[mi][0], a[mi][1], a[mi][2], a[mi][3],
                             b2[nj][0], b2[nj][1]);
        }
    }

#pragma unroll
    for (int mi = 0; mi < AM; mi++) {
        const int r0 = m0 + wm + mi * 16 + (lane >> 2);
#pragma unroll
        for (int nj = 0; nj < 4; nj++) {
            const int c = n0 + wn + nj * 8 + (lane & 3) * 2;
            float2 v0 = make_float2(acc[mi][nj][0], acc[mi][nj][1]);
            float2 v1 = make_float2(acc[mi][nj][2], acc[mi][nj][3]);
            if (EPI == 2) {
                __nv_bfloat162 p0 = __float22bfloat162_rn(v0);
                __nv_bfloat162 p1 = __float22bfloat162_rn(v1);
                __nv_bfloat16* dst = (c >= 1024) ? zout : uout;
                const int cc = (c >= 1024) ? c - 1024 : c;
                *reinterpret_cast<__nv_bfloat162*>(dst + (size_t)r0 * 1024 + cc) = p0;
                *reinterpret_cast<__nv_bfloat162*>(dst + (size_t)(r0 + 8) * 1024 + cc) = p1;
            } else if (EPI == 4 || EPI == 5) {
                if (EPI == 4) {
                    const float2 bb = *reinterpret_cast<const float2*>(res + c);
                    v0.x = softplus_f(v0.x + bb.x); v0.y = softplus_f(v0.y + bb.y);
                    v1.x = softplus_f(v1.x + bb.x); v1.y = softplus_f(v1.y + bb.y);
                }
                __nv_bfloat162 p0 = __float22bfloat162_rn(v0);
                __nv_bfloat162 p1 = __float22bfloat162_rn(v1);
                *reinterpret_cast<__nv_bfloat162*>(uout + (size_t)r0 * ldc + c) = p0;
                *reinterpret_cast<__nv_bfloat162*>(uout + (size_t)(r0 + 8) * ldc + c) = p1;
            } else {
                const size_t o0 = (size_t)r0 * ldc + c;
                const size_t o1 = (size_t)(r0 + 8) * ldc + c;
                if (EPI == 1) {
                    const float2 q0 = *reinterpret_cast<const float2*>(res + o0);
                    const float2 q1 = *reinterpret_cast<const float2*>(res + o1);
                    v0.x += q0.x; v0.y += q0.y; v1.x += q1.x; v1.y += q1.y;
                }
                *reinterpret_cast<float2*>(C + o0) = v0;
                *reinterpret_cast<float2*>(C + o1) = v1;
            }
        }
    }
}

// ============================ x_proj partial combine (float2 granularity) ============================
__global__ void xcombine(const float* __restrict__ p, __nv_bfloat16* __restrict__ out) {
    const int i = blockIdx.x * blockDim.x + threadIdx.x;   // float2 index
    const float2* q = reinterpret_cast<const float2*>(p);
    const int Q = M_ROWS * 64 / 2;
    float2 a = q[i];
#pragma unroll
    for (int s = 1; s < XSPLIT; s++) {
        const float2 b = q[i + s * Q];
        a.x += b.x; a.y += b.y;
    }
    __nv_bfloat162 pk = __float22bfloat162_rn(a);
    *reinterpret_cast<__nv_bfloat162*>(out + i * 2) =
        *reinterpret_cast<__nv_bfloat162*>(&pk);
}

// ============================ fused weight-convert + LayerNorm ============================
// blocks [0,1024): in_proj f2bf, [1024,1536): out_proj, [1536,1600): x_proj,
// [1600,1632): dt_proj, [1632,2144): LayerNorm (8 rows per block, warp per row)
__global__ void prep_kernel(const float* __restrict__ w1, __nv_bfloat16* __restrict__ o1,
                            const float* __restrict__ w2, __nv_bfloat16* __restrict__ o2,
                            const float* __restrict__ w3, __nv_bfloat16* __restrict__ o3,
                            const float* __restrict__ w4, __nv_bfloat16* __restrict__ o4,
                            const float* __restrict__ x,
                            const float* __restrict__ gamma,
                            const float* __restrict__ beta,
                            __nv_bfloat16* __restrict__ hout) {
    int blk = blockIdx.x;
    if (blk >= 1632) {
        const int row = (blk - 1632) * 8 + (threadIdx.x >> 5);
        const int lane = threadIdx.x & 31;
        const float4* xr = reinterpret_cast<const float4*>(x + (size_t)row * DIM);
        float4 v[4];
        float s = 0.f, q = 0.f;
#pragma unroll
        for (int j = 0; j < 4; j++) {
            v[j] = xr[lane + 32 * j];
            s += v[j].x + v[j].y + v[j].z + v[j].w;
            q += v[j].x * v[j].x + v[j].y * v[j].y + v[j].z * v[j].z + v[j].w * v[j].w;
        }
#pragma unroll
        for (int o = 16; o; o >>= 1) {
            s += __shfl_xor_sync(~0u, s, o);
            q += __shfl_xor_sync(~0u, q, o);
        }
        const float mean = s * (1.0f / DIM);
        const float var  = q * (1.0f / DIM) - mean * mean;
        const float inv  = rsqrtf(var + 1e-5f);
        uint2* orow = reinterpret_cast<uint2*>(hout + (size_t)row * DIM);
#pragma unroll
        for (int j = 0; j < 4; j++) {
            const float4 gv = reinterpret_cast<const float4*>(gamma)[lane + 32 * j];
            const float4 bv = reinterpret_cast<const float4*>(beta)[lane + 32 * j];
            float4 o4;
            o4.x = (v[j].x - mean) * inv * gv.x + bv.x;
            o4.y = (v[j].y - mean) * inv * gv.y + bv.y;
            o4.z = (v[j].z - mean) * inv * gv.z + bv.z;
            o4.w = (v[j].w - mean) * inv * gv.w + bv.w;
            __nv_bfloat162 p0 = __float22bfloat162_rn(make_float2(o4.x, o4.y));
            __nv_bfloat162 p1 = __float22bfloat162_rn(make_float2(o4.z, o4.w));
            uint2 pk;
            pk.x = *reinterpret_cast<uint32_t*>(&p0);
            pk.y = *reinterpret_cast<uint32_t*>(&p1);
            orow[lane + 32 * j] = pk;
        }
        return;
    }
    const float* in; __nv_bfloat16* out;
    if (blk < 1024) { in = w1; out = o1; }
    else if (blk < 1536) { in = w2; out = o2; blk -= 1024; }
    else if (blk < 1600) { in = w3; out = o3; blk -= 1536; }
    else { in = w4; out = o4; blk -= 1600; }
    const int i = blk * 256 + threadIdx.x;
    const float4 v = reinterpret_cast<const float4*>(in)[i];
    __nv_bfloat162 p0 = __float22bfloat162_rn(make_float2(v.x, v.y));
    __nv_bfloat162 p1 = __float22bfloat162_rn(make_float2(v.z, v.w));
    reinterpret_cast<__nv_bfloat162*>(out)[i * 2 + 0] = p0;
    reinterpret_cast<__nv_bfloat162*>(out)[i * 2 + 1] = p1;
}

// ============================ depthwise conv + silu (scalar, 8 l/thread) ============================
__global__ void conv_silu_kernel(const __nv_bfloat16* __restrict__ u,
                                 const float* __restrict__ cw,
                                 const float* __restrict__ cb,
                                 __nv_bfloat16* __restrict__ uabf) {
    const int d = blockIdx.x * blockDim.x + threadIdx.x;
    const int l0 = blockIdx.y * 8;
    const int b = blockIdx.z;
    const __nv_bfloat16* up = u + ((size_t)b * L_SZ + l0) * D_INNER + d;
    const float4 w = *reinterpret_cast<const float4*>(cw + d * 4);
    const float bias = cb[d];

    float v[11];
#pragma unroll
    for (int j = 0; j < 11; j++) {
        const int l = l0 + j - 3;
        v[j] = (l >= 0) ? __bfloat162float(up[(j - 3) * D_INNER]) : 0.f;
    }
#pragma unroll
    for (int j = 0; j < 8; j++) {
        float a = bias;
        a = fmaf(w.x, v[j], a);
        a = fmaf(w.y, v[j + 1], a);
        a = fmaf(w.z, v[j + 2], a);
        a = fmaf(w.w, v[j + 3], a);
        const float s = a / (1.0f + __expf(-a));
        uabf[((size_t)b * L_SZ + l0 + j) * D_INNER + d] = __float2bfloat16(s);
    }
}

// ============================ chunked parallel scan ============================
__device__ __forceinline__ void pow_ladder(float q, float* dA) {
    const float q2 = q * q;
    const float q4 = q2 * q2;
    const float q8 = q4 * q4;
    dA[0] = q;       dA[1] = q2;      dA[2] = q2 * q;  dA[3] = q4;
    dA[4] = q4 * q;  dA[5] = q4 * q2; dA[6] = dA[5] * q; dA[7] = q8;
#pragma unroll
    for (int i = 0; i < 8; i++) dA[8 + i] = q8 * dA[i];
}

__device__ __forceinline__ bool seq_check(const float* A_log, int d, float* Ac) {
    bool seq = true;
#pragma unroll
    for (int i = 0; i < 4; i++) {
        const float4 v = reinterpret_cast<const float4*>(A_log + d * 16)[i];
        Ac[i * 4 + 0] = -__expf(v.x); Ac[i * 4 + 1] = -__expf(v.y);
        Ac[i * 4 + 2] = -__expf(v.z); Ac[i * 4 + 3] = -__expf(v.w);
    }
#pragma unroll
    for (int n = 0; n < 16; n++)
        seq = seq && (fabsf(Ac[n] + (float)(n + 1)) < 1e-3f * (float)(n + 1));
    return seq;
}

__global__ void scan_p1(const __nv_bfloat16* __restrict__ delta,
                        const __nv_bfloat16* __restrict__ uact,
                        const __nv_bfloat16* __restrict__ xdbf,
                        const float* __restrict__ A_log,
                        float* __restrict__ hend,
                        float* __restrict__ sumdl) {
    const int t = blockIdx.x * blockDim.x + threadIdx.x;
    const int d = t & 1023;
    const int ch = (t >> 10) & (NCH - 1);
    const int b = t >> 15;

    float Ac[16];
    const bool seq = seq_check(A_log, d, Ac);

    const size_t rb = (size_t)(b * L_SZ + ch * CHL);
    const __nv_bfloat16* dr = delta + rb * D_INNER + d;
    const __nv_bfloat16* ur = uact + rb * D_INNER + d;
    const __nv_bfloat16* xd = xdbf + rb * 64;

    float h[16];
#pragma unroll
    for (int n = 0; n < 16; n++) h[n] = 0.f;
    float sdl = 0.f;

    if (seq) {
#pragma unroll 2
        for (int l = 0; l < CHL; l++) {
            const float dl = __bfloat162float(__ldg(dr + l * D_INNER));
            const float uv = __bfloat162float(__ldg(ur + l * D_INNER));
            float Bv[16];
            ld16bf(xd + l * 64 + DT_RANK, Bv);
            sdl += dl;
            const float du = dl * uv;
            float dA[16];
            pow_ladder(__expf(-dl), dA);
#pragma unroll
            for (int n = 0; n < 16; n++)
                h[n] = fmaf(dA[n], h[n], du * Bv[n]);
        }
    } else {
#pragma unroll 2
        for (int l = 0; l < CHL; l++) {
            const float dl = __bfloat162float(__ldg(dr + l * D_INNER));
            const float uv = __bfloat162float(__ldg(ur + l * D_INNER));
            float Bv[16];
            ld16bf(xd + l * 64 + DT_RANK, Bv);
            sdl += dl;
            const float du = dl * uv;
#pragma unroll
            for (int n = 0; n < 16; n++)
                h[n] = fmaf(__expf(dl * Ac[n]), h[n], du * Bv[n]);
        }
    }

    float4* he = reinterpret_cast<float4*>(hend + ((size_t)((b * NCH + ch) * 1024 + d)) * 16);
#pragma unroll
    for (int i = 0; i < 4; i++)
        he[i] = make_float4(h[i*4], h[i*4+1], h[i*4+2], h[i*4+3]);
    sumdl[(b * NCH + ch) * 1024 + d] = sdl;
}

__global__ void scan_p2(const float* __restrict__ hend,
                        const float* __restrict__ sumdl,
                        const float* __restrict__ A_log,
                        float* __restrict__ hin) {
    const int t = blockIdx.x * blockDim.x + threadIdx.x;
    const int n = t & 15;
    const int d = (t >> 4) & 1023;
    const int b = t >> 14;

    const float Ac = -__expf(A_log[d * 16 + n]);
    float h = 0.f;
#pragma unroll
    for (int ch = 0; ch < NCH; ch++) {
        const size_t ix = ((size_t)((b * NCH + ch) * 1024 + d)) * 16 + n;
        hin[ix] = h;
        const float P = __expf(Ac * sumdl[(b * NCH + ch) * 1024 + d]);
        h = fmaf(P, h, hend[ix]);
    }
}

__global__ void scan_p3(const __nv_bfloat16* __restrict__ delta,
                        const __nv_bfloat16* __restrict__ uact,
                        const __nv_bfloat16* __restrict__ xdbf,
                        const __nv_bfloat16* __restrict__ zbf,
                        const float* __restrict__ A_log,
                        const float* __restrict__ Dp,
                        const float* __restrict__ hin,
                        __nv_bfloat16* __restrict__ yg) {
    const int t = blockIdx.x * blockDim.x + threadIdx.x;
    const int d = t & 1023;
    const int ch = (t >> 10) & (NCH - 1);
    const int b = t >> 15;

    float Ac[16];
    const bool seq = seq_check(A_log, d, Ac);
    const float Dd = Dp[d];

    float h[16];
    const float4* hi = reinterpret_cast<const float4*>(
        hin + ((size_t)((b * NCH + ch) * 1024 + d)) * 16);
#pragma unroll
    for (int i = 0; i < 4; i++) {
        const float4 v = hi[i];
        h[i*4+0]=v.x; h[i*4+1]=v.y; h[i*4+2]=v.z; h[i*4+3]=v.w;
    }

    const size_t rb = (size_t)(b * L_SZ + ch * CHL);
    const __nv_bfloat16* dr = delta + rb * D_INNER + d;
    const __nv_bfloat16* ur = uact + rb * D_INNER + d;
    const __nv_bfloat16* xd = xdbf + rb * 64;
    const __nv_bfloat16* zr = zbf + rb * D_INNER + d;
    __nv_bfloat16* yo = yg + rb * D_INNER + d;

#pragma unroll 2
    for (int l = 0; l < CHL; l++) {
        const float dl = __bfloat162float(__ldg(dr + l * D_INNER));
        const float uv = __bfloat162float(__ldg(ur + l * D_INNER));
        float Bv[16], Cv[16];
        ld16bf(xd + l * 64 + DT_RANK, Bv);
        ld16bf(xd + l * 64 + DT_RANK + D_STATE, Cv);
        const float du = dl * uv;
        float yv = 0.f;
        if (seq) {
            float dA[16];
            pow_ladder(__expf(-dl), dA);
#pragma unroll
            for (int n = 0; n < 16; n++) {
                h[n] = fmaf(dA[n], h[n], du * Bv[n]);
                yv = fmaf(h[n], Cv[n], yv);
            }
        } else {
#pragma unroll
            for (int n = 0; n < 16; n++) {
                h[n] = fmaf(__expf(dl * Ac[n]), h[n], du * Bv[n]);
                yv = fmaf(h[n], Cv[n], yv);
            }
        }
        const float z = __bfloat162float(zr[l * D_INNER]);
        const float sg = z / (1.0f + __expf(-z));
        yo[l * D_INNER] = __float2bfloat16((yv + uv * Dd) * sg);
    }
}

// ============================ launch ============================
extern "C" void kernel_launch(void* const* d_in, const int* in_sizes, int n_in,
                              void* d_out, int out_size) {
    const float* x         = (const float*)d_in[0];
    const float* gamma     = (const float*)d_in[2];
    const float* beta      = (const float*)d_in[3];
    const float* in_proj_w = (const float*)d_in[4];
    const float* conv_w    = (const float*)d_in[5];
    const float* conv_b    = (const float*)d_in[6];
    const float* x_proj_w  = (const float*)d_in[7];
    const float* dt_proj_w = (const float*)d_in[8];
    const float* dt_proj_b = (const float*)d_in[9];
    const float* A_log     = (const float*)d_in[10];
    const float* Dp        = (const float*)d_in[11];
    const float* out_proj_w= (const float*)d_in[12];
    float* out = (float*)d_out;

    __nv_bfloat16 *hbf_, *wib_, *wob_, *wxb_, *wdt_, *ubf_, *zbf_, *uabf_, *xdbf_, *dlbf_, *ygbf_;
    float *xp_, *he_, *sd_, *hi_;
    cudaGetSymbolAddress((void**)&hbf_, g_hbf);
    cudaGetSymbolAddress((void**)&wib_, g_wib);
    cudaGetSymbolAddress((void**)&wob_, g_wob);
    cudaGetSymbolAddress((void**)&wxb_, g_wxb);
    cudaGetSymbolAddress((void**)&wdt_, g_wdt);
    cudaGetSymbolAddress((void**)&ubf_, g_ubf);
    cudaGetSymbolAddress((void**)&zbf_, g_zbf);
    cudaGetSymbolAddress((void**)&uabf_, g_uabf);
    cudaGetSymbolAddress((void**)&xp_, g_xpart);
    cudaGetSymbolAddress((void**)&xdbf_, g_xdbf);
    cudaGetSymbolAddress((void**)&dlbf_, g_dlbf);
    cudaGetSymbolAddress((void**)&ygbf_, g_ygbf);
    cudaGetSymbolAddress((void**)&he_, g_hend);
    cudaGetSymbolAddress((void**)&sd_, g_sumdl);
    cudaGetSymbolAddress((void**)&hi_, g_hin);

    cudaFuncSetAttribute(hmma_gemm<128, 2, 0>,
                         cudaFuncAttributeMaxDynamicSharedMemorySize, 61440);

    // 0+1. weight conversions + LayerNorm (single launch)
    prep_kernel<<<2144, 256>>>(in_proj_w, wib_, out_proj_w, wob_,
                               x_proj_w, wxb_, dt_proj_w, wdt_,
                               x, gamma, beta, hbf_);

    // 2. in_proj: u | z both bf16, K=512, BN=128
    hmma_gemm<128, 2, 0><<<dim3(16, 32), 256, 61440>>>(
        hbf_, DIM, wib_, DIM, nullptr, 1024, DIM, nullptr, ubf_, zbf_);

    // 3. depthwise conv + silu (scalar, 8 l/thread)
    conv_silu_kernel<<<dim3(4, L_SZ / 8, B_SZ), 256>>>(ubf_, conv_w, conv_b, uabf_);

    // 4. x_proj: K split 8x128 into private partials, then combine -> bf16
    hmma_gemm<64, 0, 128><<<dim3(1, 32, XSPLIT), 256, 46080>>>(
        uabf_, D_INNER, wxb_, D_INNER, xp_, 64, D_INNER, nullptr, nullptr, nullptr);
    xcombine<<<M_ROWS * 64 / 2 / 256, 256>>>(xp_, xdbf_);

    // 5. dt_proj + softplus -> bf16 delta, K=32
    hmma_gemm<64, 4, 0><<<dim3(16, 32), 256, 46080>>>(
        xdbf_, 64, wdt_, DT_RANK, nullptr, 1024, DT_RANK, dt_proj_b, dlbf_, nullptr);

    // 6. chunked scan (3 passes, NCH=32)
    scan_p1<<<B_SZ * NCH * D_INNER / 256, 256>>>(dlbf_, uabf_, xdbf_, A_log, he_, sd_);
    scan_p2<<<B_SZ * D_INNER * D_STATE / 256, 256>>>(he_, sd_, A_log, hi_);
    scan_p3<<<B_SZ * NCH * D_INNER / 256, 256>>>(dlbf_, uabf_, xdbf_, zbf_, A_log, Dp,
                                                 hi_, ygbf_);

    // 7. out_proj + residual
    hmma_gemm<64, 1, 0><<<dim3(DIM / 64, 32), 256, 46080>>>(
        ygbf_, D_INNER, wob_, D_INNER, out, DIM, D_INNER, x, nullptr, nullptr);
}

// round 15
// speedup vs baseline: 1.3207x; 1.0447x over previous
#include <cuda_runtime.h>
#include <cuda_bf16.h>
#include <math.h>
#include <stdint.h>

#define B_SZ 2
#define L_SZ 2048
#define DIM 512
#define D_INNER 1024
#define D_STATE 16
#define DT_RANK 32
#define M_ROWS (B_SZ * L_SZ)   // 4096
#define NCH 32                  // scan chunks
#define CHL (L_SZ / NCH)        // 64 timesteps per chunk
#define XSPLIT 8                // x_proj K-split factor

// -------- scratch (device globals; no allocation allowed) --------
__device__ __nv_bfloat16 g_hbf[M_ROWS * DIM];
__device__ __nv_bfloat16 g_wib[2 * D_INNER * DIM];
__device__ __nv_bfloat16 g_wob[DIM * D_INNER];
__device__ __nv_bfloat16 g_wxb[64 * D_INNER];
__device__ __nv_bfloat16 g_wdt[D_INNER * DT_RANK + 16];
__device__ __nv_bfloat16 g_ubf[M_ROWS * D_INNER];
__device__ __nv_bfloat16 g_zsil[M_ROWS * D_INNER];     // pre-gated silu(z)
__device__ __nv_bfloat16 g_uabf[M_ROWS * D_INNER];
__device__ float g_xpart[XSPLIT * M_ROWS * 64];
__device__ __nv_bfloat16 g_xdbf[M_ROWS * 64 + 16];
__device__ __nv_bfloat16 g_dlbf[M_ROWS * D_INNER];
__device__ __nv_bfloat16 g_ygbf[M_ROWS * D_INNER];
__device__ float g_hend[B_SZ * NCH * D_INNER * D_STATE];
__device__ float g_sumdl[B_SZ * NCH * D_INNER];
__device__ float g_hin[B_SZ * NCH * D_INNER * D_STATE];

// ============================ PTX helpers ============================
__device__ __forceinline__ uint32_t smem_u32(const void* p) {
    uint32_t a;
    asm("{ .reg .u64 t; cvta.to.shared.u64 t, %1; cvt.u32.u64 %0, t; }"
        : "=r"(a) : "l"(p));
    return a;
}
__device__ __forceinline__ void ldsm_x4(uint32_t& r0, uint32_t& r1,
                                        uint32_t& r2, uint32_t& r3, uint32_t a) {
    asm volatile("ldmatrix.sync.aligned.m8n8.x4.shared.b16 {%0,%1,%2,%3}, [%4];"
                 : "=r"(r0), "=r"(r1), "=r"(r2), "=r"(r3) : "r"(a));
}
__device__ __forceinline__ void mma16816(float* c, uint32_t a0, uint32_t a1,
                                         uint32_t a2, uint32_t a3,
                                         uint32_t b0, uint32_t b1) {
    asm volatile(
        "mma.sync.aligned.m16n8k16.row.col.f32.bf16.bf16.f32 "
        "{%0,%1,%2,%3}, {%4,%5,%6,%7}, {%8,%9}, {%0,%1,%2,%3};"
        : "+f"(c[0]), "+f"(c[1]), "+f"(c[2]), "+f"(c[3])
        : "r"(a0), "r"(a1), "r"(a2), "r"(a3), "r"(b0), "r"(b1));
}
__device__ __forceinline__ void cp16(uint32_t dst, const void* src) {
    asm volatile("cp.async.cg.shared.global [%0], [%1], 16;" :: "r"(dst), "l"(src));
}
__device__ __forceinline__ void cp_commit() {
    asm volatile("cp.async.commit_group;" ::: "memory");
}
__device__ __forceinline__ void cp_wait1() {
    asm volatile("cp.async.wait_group 1;" ::: "memory");
}
__device__ __forceinline__ float softplus_f(float x) {
    return x > 20.f ? x : log1pf(expf(x));
}
__device__ __forceinline__ void ld16bf(const __nv_bfloat16* p, float* o) {
    union { uint4 u; __nv_bfloat162 h[4]; } A, B;
    A.u = *reinterpret_cast<const uint4*>(p);
    B.u = *reinterpret_cast<const uint4*>(p + 8);
#pragma unroll
    for (int i = 0; i < 4; i++) {
        float2 f = __bfloat1622float2(A.h[i]);
        o[i * 2] = f.x; o[i * 2 + 1] = f.y;
        f = __bfloat1622float2(B.h[i]);
        o[8 + i * 2] = f.x; o[8 + i * 2 + 1] = f.y;
    }
}

// ============================ HMMA bf16 GEMM (3-stage pipeline) ============================
// EPI: 0 fp32 (SPLITK partials), 1 fp32+residual, 2 split u/silu(z) bf16,
//      4 softplus(acc+bias)->bf16, 5 bf16
template <int BN, int EPI, int SPLITK>
__global__ void __launch_bounds__(256)
hmma_gemm(const __nv_bfloat16* __restrict__ A, int lda,
          const __nv_bfloat16* __restrict__ W, int ldw,
          float* __restrict__ C, int ldc, int K,
          const float* __restrict__ res,
          __nv_bfloat16* __restrict__ uout,
          __nv_bfloat16* __restrict__ zout) {
    constexpr int AM = (BN == 128) ? 4 : 2;
    constexpr int STG = (128 + BN) * 80;
    constexpr int CH_TOT = (128 + BN) * 5;
    extern __shared__ __align__(16) char sm[];

    const int tid = threadIdx.x;
    const int lane = tid & 31;
    const int wid = tid >> 5;
    const int m0 = blockIdx.y * 128;
    const int n0 = blockIdx.x * BN;
    const int wm = (BN == 128) ? (wid & 1) * 64 : (wid & 3) * 32;
    const int wn = (BN == 128) ? (wid >> 1) * 32 : (wid >> 2) * 32;

    if (SPLITK) {
        const int kz = blockIdx.z * SPLITK;
        A += kz; W += kz;
        C += (size_t)blockIdx.z * M_ROWS * 64;   // private partial buffer
    }
    const int KT = (SPLITK ? SPLITK : K) >> 5;

    const uint32_t smb = smem_u32(sm);

    uint32_t aoff[AM], boff[2];
#pragma unroll
    for (int mi = 0; mi < AM; mi++)
        aoff[mi] = (uint32_t)(wm + mi * 16 + (lane & 15)) * 80 + ((lane >> 4) & 1) * 16;
#pragma unroll
    for (int ni = 0; ni < 2; ni++)
        boff[ni] = 128 * 80
                 + (uint32_t)(wn + ni * 16 + (lane & 7) + ((lane >> 4) & 1) * 8) * 80
                 + ((lane >> 3) & 1) * 16;

    float acc[AM][4][4];
#pragma unroll
    for (int i = 0; i < AM; i++)
#pragma unroll
        for (int j = 0; j < 4; j++)
#pragma unroll
            for (int q = 0; q < 4; q++) acc[i][j][q] = 0.f;

    auto load_stage = [&](int kt, int st) {
        const int k0 = kt * 32;
        const uint32_t base = smb + st * STG;
        for (int c = tid; c < CH_TOT; c += 256) {
            const int row = c / 5, col = c % 5;
            const uint32_t dst = base + row * 80 + col * 16;
            if (row < 128)
                cp16(dst, A + (size_t)(m0 + row) * lda + k0 + col * 8);
            else
                cp16(dst, W + (size_t)(n0 + row - 128) * ldw + k0 + col * 8);
        }
    };

    load_stage(0, 0); cp_commit();
    if (KT > 1) { load_stage(1, 1); cp_commit(); }
    else cp_commit();

    for (int kt = 0; kt < KT; kt++) {
        cp_wait1();
        __syncthreads();
        if (kt + 2 < KT) load_stage(kt + 2, (kt + 2) % 3);
        cp_commit();

        const uint32_t sbase = smb + (kt % 3) * STG;
#pragma unroll
        for (int kk = 0; kk < 2; kk++) {
            const uint32_t ko = kk * 32;
            uint32_t a[AM][4], b2[4][2];
#pragma unroll
            for (int mi = 0; mi < AM; mi++)
                ldsm_x4(a[mi][0], a[mi][1], a[mi][2], a[mi][3], sbase + aoff[mi] + ko);
#pragma unroll
            for (int ni = 0; ni < 2; ni++) {
                uint32_t r0, r1, r2, r3;
                ldsm_x4(r0, r1, r2, r3, sbase + boff[ni] + ko);
                b2[ni * 2 + 0][0] = r0; b2[ni * 2 + 0][1] = r1;
                b2[ni * 2 + 1][0] = r2; b2[ni * 2 + 1][1] = r3;
            }
#pragma unroll
            for (int mi = 0; mi < AM; mi++)
#pragma unroll
                for (int nj = 0; nj < 4; nj++)
                    mma16816(acc[mi][nj], a[mi][0], a[mi][1], a[mi][2], a[mi][3],
                             b2[nj][0], b2[nj][1]);
        }
    }

#pragma unroll
    for (int mi = 0; mi < AM; mi++) {
        const int r0 = m0 + wm + mi * 16 + (lane >> 2);
#pragma unroll
        for (int nj = 0; nj < 4; nj++) {
            const int c = n0 + wn + nj * 8 + (lane & 3) * 2;
            float2 v0 = make_float2(acc[mi][nj][0], acc[mi][nj][1]);
            float2 v1 = make_float2(acc[mi][nj][2], acc[mi][nj][3]);
            if (EPI == 2) {
                __nv_bfloat16* dst;
                int cc = c;
                if (c >= 1024) {
                    // pre-gate: silu(z) in fp32
                    v0.x = v0.x / (1.0f + __expf(-v0.x));
                    v0.y = v0.y / (1.0f + __expf(-v0.y));
                    v1.x = v1.x / (1.0f + __expf(-v1.x));
                    v1.y = v1.y / (1.0f + __expf(-v1.y));
                    dst = zout; cc = c - 1024;
                } else {
                    dst = uout;
                }
                __nv_bfloat162 p0 = __float22bfloat162_rn(v0);
                __nv_bfloat162 p1 = __float22bfloat162_rn(v1);
                *reinterpret_cast<__nv_bfloat162*>(dst + (size_t)r0 * 1024 + cc) = p0;
                *reinterpret_cast<__nv_bfloat162*>(dst + (size_t)(r0 + 8) * 1024 + cc) = p1;
            } else if (EPI == 4 || EPI == 5) {
                if (EPI == 4) {
                    const float2 bb = *reinterpret_cast<const float2*>(res + c);
                    v0.x = softplus_f(v0.x + bb.x); v0.y = softplus_f(v0.y + bb.y);
                    v1.x = softplus_f(v1.x + bb.x); v1.y = softplus_f(v1.y + bb.y);
                }
                __nv_bfloat162 p0 = __float22bfloat162_rn(v0);
                __nv_bfloat162 p1 = __float22bfloat162_rn(v1);
                *reinterpret_cast<__nv_bfloat162*>(uout + (size_t)r0 * ldc + c) = p0;
                *reinterpret_cast<__nv_bfloat162*>(uout + (size_t)(r0 + 8) * ldc + c) = p1;
            } else {
                const size_t o0 = (size_t)r0 * ldc + c;
                const size_t o1 = (size_t)(r0 + 8) * ldc + c;
                if (EPI == 1) {
                    const float2 q0 = *reinterpret_cast<const float2*>(res + o0);
                    const float2 q1 = *reinterpret_cast<const float2*>(res + o1);
                    v0.x += q0.x; v0.y += q0.y; v1.x += q1.x; v1.y += q1.y;
                }
                *reinterpret_cast<float2*>(C + o0) = v0;
                *reinterpret_cast<float2*>(C + o1) = v1;
            }
        }
    }
}

// ============================ x_proj partial combine (float2 granularity) ============================
__global__ void xcombine(const float* __restrict__ p, __nv_bfloat16* __restrict__ out) {
    const int i = blockIdx.x * blockDim.x + threadIdx.x;   // float2 index
    const float2* q = reinterpret_cast<const float2*>(p);
    const int Q = M_ROWS * 64 / 2;
    float2 a = q[i];
#pragma unroll
    for (int s = 1; s < XSPLIT; s++) {
        const float2 b = q[i + s * Q];
        a.x += b.x; a.y += b.y;
    }
    __nv_bfloat162 pk = __float22bfloat162_rn(a);
    *reinterpret_cast<__nv_bfloat162*>(out + i * 2) =
        *reinterpret_cast<__nv_bfloat162*>(&pk);
}

// ============================ fused weight-convert + LayerNorm ============================
__global__ void prep_kernel(const float* __restrict__ w1, __nv_bfloat16* __restrict__ o1,
                            const float* __restrict__ w2, __nv_bfloat16* __restrict__ o2,
                            const float* __restrict__ w3, __nv_bfloat16* __restrict__ o3,
                            const float* __restrict__ w4, __nv_bfloat16* __restrict__ o4,
                            const float* __restrict__ x,
                            const float* __restrict__ gamma,
                            const float* __restrict__ beta,
                            __nv_bfloat16* __restrict__ hout) {
    int blk = blockIdx.x;
    if (blk >= 1632) {
        const int row = (blk - 1632) * 8 + (threadIdx.x >> 5);
        const int lane = threadIdx.x & 31;
        const float4* xr = reinterpret_cast<const float4*>(x + (size_t)row * DIM);
        float4 v[4];
        float s = 0.f, q = 0.f;
#pragma unroll
        for (int j = 0; j < 4; j++) {
            v[j] = xr[lane + 32 * j];
            s += v[j].x + v[j].y + v[j].z + v[j].w;
            q += v[j].x * v[j].x + v[j].y * v[j].y + v[j].z * v[j].z + v[j].w * v[j].w;
        }
#pragma unroll
        for (int o = 16; o; o >>= 1) {
            s += __shfl_xor_sync(~0u, s, o);
            q += __shfl_xor_sync(~0u, q, o);
        }
        const float mean = s * (1.0f / DIM);
        const float var  = q * (1.0f / DIM) - mean * mean;
        const float inv  = rsqrtf(var + 1e-5f);
        uint2* orow = reinterpret_cast<uint2*>(hout + (size_t)row * DIM);
#pragma unroll
        for (int j = 0; j < 4; j++) {
            const float4 gv = reinterpret_cast<const float4*>(gamma)[lane + 32 * j];
            const float4 bv = reinterpret_cast<const float4*>(beta)[lane + 32 * j];
            float4 o4;
            o4.x = (v[j].x - mean) * inv * gv.x + bv.x;
            o4.y = (v[j].y - mean) * inv * gv.y + bv.y;
            o4.z = (v[j].z - mean) * inv * gv.z + bv.z;
            o4.w = (v[j].w - mean) * inv * gv.w + bv.w;
            __nv_bfloat162 p0 = __float22bfloat162_rn(make_float2(o4.x, o4.y));
            __nv_bfloat162 p1 = __float22bfloat162_rn(make_float2(o4.z, o4.w));
            uint2 pk;
            pk.x = *reinterpret_cast<uint32_t*>(&p0);
            pk.y = *reinterpret_cast<uint32_t*>(&p1);
            orow[lane + 32 * j] = pk;
        }
        return;
    }
    const float* in; __nv_bfloat16* out;
    if (blk < 1024) { in = w1; out = o1; }
    else if (blk < 1536) { in = w2; out = o2; blk -= 1024; }
    else if (blk < 1600) { in = w3; out = o3; blk -= 1536; }
    else { in = w4; out = o4; blk -= 1600; }
    const int i = blk * 256 + threadIdx.x;
    const float4 v = reinterpret_cast<const float4*>(in)[i];
    __nv_bfloat162 p0 = __float22bfloat162_rn(make_float2(v.x, v.y));
    __nv_bfloat162 p1 = __float22bfloat162_rn(make_float2(v.z, v.w));
    reinterpret_cast<__nv_bfloat162*>(out)[i * 2 + 0] = p0;
    reinterpret_cast<__nv_bfloat162*>(out)[i * 2 + 1] = p1;
}

// ============================ depthwise conv + silu (scalar, 8 l/thread) ============================
__global__ void conv_silu_kernel(const __nv_bfloat16* __restrict__ u,
                                 const float* __restrict__ cw,
                                 const float* __restrict__ cb,
                                 __nv_bfloat16* __restrict__ uabf) {
    const int d = blockIdx.x * blockDim.x + threadIdx.x;
    const int l0 = blockIdx.y * 8;
    const int b = blockIdx.z;
    const __nv_bfloat16* up = u + ((size_t)b * L_SZ + l0) * D_INNER + d;
    const float4 w = *reinterpret_cast<const float4*>(cw + d * 4);
    const float bias = cb[d];

    float v[11];
#pragma unroll
    for (int j = 0; j < 11; j++) {
        const int l = l0 + j - 3;
        v[j] = (l >= 0) ? __bfloat162float(up[(j - 3) * D_INNER]) : 0.f;
    }
#pragma unroll
    for (int j = 0; j < 8; j++) {
        float a = bias;
        a = fmaf(w.x, v[j], a);
        a = fmaf(w.y, v[j + 1], a);
        a = fmaf(w.z, v[j + 2], a);
        a = fmaf(w.w, v[j + 3], a);
        const float s = a / (1.0f + __expf(-a));
        uabf[((size_t)b * L_SZ + l0 + j) * D_INNER + d] = __float2bfloat16(s);
    }
}

// ============================ chunked parallel scan ============================
__device__ __forceinline__ void pow_ladder(float q, float* dA) {
    const float q2 = q * q;
    const float q4 = q2 * q2;
    const float q8 = q4 * q4;
    dA[0] = q;       dA[1] = q2;      dA[2] = q2 * q;  dA[3] = q4;
    dA[4] = q4 * q;  dA[5] = q4 * q2; dA[6] = dA[5] * q; dA[7] = q8;
#pragma unroll
    for (int i = 0; i < 8; i++) dA[8 + i] = q8 * dA[i];
}

__device__ __forceinline__ bool seq_check(const float* A_log, int d, float* Ac) {
    bool seq = true;
#pragma unroll
    for (int i = 0; i < 4; i++) {
        const float4 v = reinterpret_cast<const float4*>(A_log + d * 16)[i];
        Ac[i * 4 + 0] = -__expf(v.x); Ac[i * 4 + 1] = -__expf(v.y);
        Ac[i * 4 + 2] = -__expf(v.z); Ac[i * 4 + 3] = -__expf(v.w);
    }
#pragma unroll
    for (int n = 0; n < 16; n++)
        seq = seq && (fabsf(Ac[n] + (float)(n + 1)) < 1e-3f * (float)(n + 1));
    return seq;
}

__global__ void scan_p1(const __nv_bfloat16* __restrict__ delta,
                        const __nv_bfloat16* __restrict__ uact,
                        const __nv_bfloat16* __restrict__ xdbf,
                        const float* __restrict__ A_log,
                        float* __restrict__ hend,
                        float* __restrict__ sumdl) {
    const int t = blockIdx.x * blockDim.x + threadIdx.x;
    const int d = t & 1023;
    const int ch = (t >> 10) & (NCH - 1);
    const int b = t >> 15;

    float Ac[16];
    const bool seq = seq_check(A_log, d, Ac);

    const size_t rb = (size_t)(b * L_SZ + ch * CHL);
    const __nv_bfloat16* dr = delta + rb * D_INNER + d;
    const __nv_bfloat16* ur = uact + rb * D_INNER + d;
    const __nv_bfloat16* xd = xdbf + rb * 64;

    float h[16];
#pragma unroll
    for (int n = 0; n < 16; n++) h[n] = 0.f;
    float sdl = 0.f;

    if (seq) {
#pragma unroll 2
        for (int l = 0; l < CHL; l++) {
            const float dl = __bfloat162float(__ldg(dr + l * D_INNER));
            const float uv = __bfloat162float(__ldg(ur + l * D_INNER));
            float Bv[16];
            ld16bf(xd + l * 64 + DT_RANK, Bv);
            sdl += dl;
            const float du = dl * uv;
            float dA[16];
            pow_ladder(__expf(-dl), dA);
#pragma unroll
            for (int n = 0; n < 16; n++)
                h[n] = fmaf(dA[n], h[n], du * Bv[n]);
        }
    } else {
#pragma unroll 2
        for (int l = 0; l < CHL; l++) {
            const float dl = __bfloat162float(__ldg(dr + l * D_INNER));
            const float uv = __bfloat162float(__ldg(ur + l * D_INNER));
            float Bv[16];
            ld16bf(xd + l * 64 + DT_RANK, Bv);
            sdl += dl;
            const float du = dl * uv;
#pragma unroll
            for (int n = 0; n < 16; n++)
                h[n] = fmaf(__expf(dl * Ac[n]), h[n], du * Bv[n]);
        }
    }

    float4* he = reinterpret_cast<float4*>(hend + ((size_t)((b * NCH + ch) * 1024 + d)) * 16);
#pragma unroll
    for (int i = 0; i < 4; i++)
        he[i] = make_float4(h[i*4], h[i*4+1], h[i*4+2], h[i*4+3]);
    sumdl[(b * NCH + ch) * 1024 + d] = sdl;
}

__global__ void scan_p2(const float* __restrict__ hend,
                        const float* __restrict__ sumdl,
                        const float* __restrict__ A_log,
                        float* __restrict__ hin) {
    const int t = blockIdx.x * blockDim.x + threadIdx.x;
    const int n = t & 15;
    const int d = (t >> 4) & 1023;
    const int b = t >> 14;

    const float Ac = -__expf(A_log[d * 16 + n]);
    float h = 0.f;
#pragma unroll
    for (int ch = 0; ch < NCH; ch++) {
        const size_t ix = ((size_t)((b * NCH + ch) * 1024 + d)) * 16 + n;
        hin[ix] = h;
        const float P = __expf(Ac * sumdl[(b * NCH + ch) * 1024 + d]);
        h = fmaf(P, h, hend[ix]);
    }
}

__global__ void scan_p3(const __nv_bfloat16* __restrict__ delta,
                        const __nv_bfloat16* __restrict__ uact,
                        const __nv_bfloat16* __restrict__ xdbf,
                        const __nv_bfloat16* __restrict__ zsil,
                        const float* __restrict__ A_log,
                        const float* __restrict__ Dp,
                        const float* __restrict__ hin,
                        __nv_bfloat16* __restrict__ yg) {
    const int t = blockIdx.x * blockDim.x + threadIdx.x;
    const int d = t & 1023;
    const int ch = (t >> 10) & (NCH - 1);
    const int b = t >> 15;

    float Ac[16];
    const bool seq = seq_check(A_log, d, Ac);
    const float Dd = Dp[d];

    float h[16];
    const float4* hi = reinterpret_cast<const float4*>(
        hin + ((size_t)((b * NCH + ch) * 1024 + d)) * 16);
#pragma unroll
    for (int i = 0; i < 4; i++) {
        const float4 v = hi[i];
        h[i*4+0]=v.x; h[i*4+1]=v.y; h[i*4+2]=v.z; h[i*4+3]=v.w;
    }

    const size_t rb = (size_t)(b * L_SZ + ch * CHL);
    const __nv_bfloat16* dr = delta + rb * D_INNER + d;
    const __nv_bfloat16* ur = uact + rb * D_INNER + d;
    const __nv_bfloat16* xd = xdbf + rb * 64;
    const __nv_bfloat16* zr = zsil + rb * D_INNER + d;
    __nv_bfloat16* yo = yg + rb * D_INNER + d;

#pragma unroll 2
    for (int l = 0; l < CHL; l++) {
        const float dl = __bfloat162float(__ldg(dr + l * D_INNER));
        const float uv = __bfloat162float(__ldg(ur + l * D_INNER));
        float Bv[16], Cv[16];
        ld16bf(xd + l * 64 + DT_RANK, Bv);
        ld16bf(xd + l * 64 + DT_RANK + D_STATE, Cv);
        const float du = dl * uv;
        float yv = 0.f;
        if (seq) {
            float dA[16];
            pow_ladder(__expf(-dl), dA);
#pragma unroll
            for (int n = 0; n < 16; n++) {
                h[n] = fmaf(dA[n], h[n], du * Bv[n]);
                yv = fmaf(h[n], Cv[n], yv);
            }
        } else {
#pragma unroll
            for (int n = 0; n < 16; n++) {
                h[n] = fmaf(__expf(dl * Ac[n]), h[n], du * Bv[n]);
                yv = fmaf(h[n], Cv[n], yv);
            }
        }
        const float sg = __bfloat162float(zr[l * D_INNER]);   // pre-gated silu(z)
        yo[l * D_INNER] = __float2bfloat16((yv + uv * Dd) * sg);
    }
}

// ============================ launch ============================
extern "C" void kernel_launch(void* const* d_in, const int* in_sizes, int n_in,
                              void* d_out, int out_size) {
    const float* x         = (const float*)d_in[0];
    const float* gamma     = (const float*)d_in[2];
    const float* beta      = (const float*)d_in[3];
    const float* in_proj_w = (const float*)d_in[4];
    const float* conv_w    = (const float*)d_in[5];
    const float* conv_b    = (const float*)d_in[6];
    const float* x_proj_w  = (const float*)d_in[7];
    const float* dt_proj_w = (const float*)d_in[8];
    const float* dt_proj_b = (const float*)d_in[9];
    const float* A_log     = (const float*)d_in[10];
    const float* Dp        = (const float*)d_in[11];
    const float* out_proj_w= (const float*)d_in[12];
    float* out = (float*)d_out;

    __nv_bfloat16 *hbf_, *wib_, *wob_, *wxb_, *wdt_, *ubf_, *zs_, *uabf_, *xdbf_, *dlbf_, *ygbf_;
    float *xp_, *he_, *sd_, *hi_;
    cudaGetSymbolAddress((void**)&hbf_, g_hbf);
    cudaGetSymbolAddress((void**)&wib_, g_wib);
    cudaGetSymbolAddress((void**)&wob_, g_wob);
    cudaGetSymbolAddress((void**)&wxb_, g_wxb);
    cudaGetSymbolAddress((void**)&wdt_, g_wdt);
    cudaGetSymbolAddress((void**)&ubf_, g_ubf);
    cudaGetSymbolAddress((void**)&zs_, g_zsil);
    cudaGetSymbolAddress((void**)&uabf_, g_uabf);
    cudaGetSymbolAddress((void**)&xp_, g_xpart);
    cudaGetSymbolAddress((void**)&xdbf_, g_xdbf);
    cudaGetSymbolAddress((void**)&dlbf_, g_dlbf);
    cudaGetSymbolAddress((void**)&ygbf_, g_ygbf);
    cudaGetSymbolAddress((void**)&he_, g_hend);
    cudaGetSymbolAddress((void**)&sd_, g_sumdl);
    cudaGetSymbolAddress((void**)&hi_, g_hin);

    cudaFuncSetAttribute(hmma_gemm<128, 2, 0>,
                         cudaFuncAttributeMaxDynamicSharedMemorySize, 61440);

    // 0+1. weight conversions + LayerNorm (single launch)
    prep_kernel<<<2144, 256>>>(in_proj_w, wib_, out_proj_w, wob_,
                               x_proj_w, wxb_, dt_proj_w, wdt_,
                               x, gamma, beta, hbf_);

    // 2. in_proj: u | silu(z) both bf16, K=512, BN=128
    hmma_gemm<128, 2, 0><<<dim3(16, 32), 256, 61440>>>(
        hbf_, DIM, wib_, DIM, nullptr, 1024, DIM, nullptr, ubf_, zs_);

    // 3. depthwise conv + silu (scalar, 8 l/thread)
    conv_silu_kernel<<<dim3(4, L_SZ / 8, B_SZ), 256>>>(ubf_, conv_w, conv_b, uabf_);

    // 4. x_proj: K split 8x128 into private partials, then combine -> bf16
    hmma_gemm<64, 0, 128><<<dim3(1, 32, XSPLIT), 256, 46080>>>(
        uabf_, D_INNER, wxb_, D_INNER, xp_, 64, D_INNER, nullptr, nullptr, nullptr);
    xcombine<<<M_ROWS * 64 / 2 / 256, 256>>>(xp_, xdbf_);

    // 5. dt_proj + softplus -> bf16 delta, K=32
    hmma_gemm<64, 4, 0><<<dim3(16, 32), 256, 46080>>>(
        xdbf_, 64, wdt_, DT_RANK, nullptr, 1024, DT_RANK, dt_proj_b, dlbf_, nullptr);

    // 6. chunked scan (3 passes, NCH=32; p2 spread over 256 blocks)
    scan_p1<<<B_SZ * NCH * D_INNER / 256, 256>>>(dlbf_, uabf_, xdbf_, A_log, he_, sd_);
    scan_p2<<<B_SZ * D_INNER * D_STATE / 128, 128>>>(he_, sd_, A_log, hi_);
    scan_p3<<<B_SZ * NCH * D_INNER / 256, 256>>>(dlbf_, uabf_, xdbf_, zs_, A_log, Dp,
                                                 hi_, ygbf_);

    // 7. out_proj + residual
    hmma_gemm<64, 1, 0><<<dim3(DIM / 64, 32), 256, 46080>>>(
        ygbf_, D_INNER, wob_, D_INNER, out, DIM, D_INNER, x, nullptr, nullptr);
}